// round 4
// baseline (speedup 1.0000x reference)
#include <cuda_runtime.h>
#include <cuda_bf16.h>
#include <cstdint>

#define MROWS 4096
#define NDIM  4096
#define MDIM  4096

// ---------------- GEMM tiling ----------------
#define BM 128
#define BN 128
#define BK 64                       // two k32 blocks per stage
#define STAGES 3
#define NKCHUNK (NDIM / BK)         // 64

// smem: per stage 4 arrays (A1,A2,B1,B2): [2 kblk][128 rows][48B (32 data + 16 pad)]
#define ROWB       48
#define KBLK_BYTES (128 * ROWB)         // 6144
#define ARR_BYTES  (2 * KBLK_BYTES)     // 12288
#define STAGE_BYTES (4 * ARR_BYTES)     // 49152
#define SMEM_TOTAL (STAGES * STAGE_BYTES)   // 147456

// Scratch: int8 digit arrays + per-row scales (allocation-free rule)
__device__ int8_t g_X1[(size_t)MROWS * NDIM];
__device__ int8_t g_X2[(size_t)MROWS * NDIM];
__device__ int8_t g_W1[(size_t)MDIM * NDIM];
__device__ int8_t g_W2[(size_t)MDIM * NDIM];
__device__ float  g_sx[MROWS];
__device__ float  g_sw[MDIM];

// ---------------- PTX helpers ----------------
__device__ __forceinline__ uint32_t smem_u32(const void* p) {
    uint32_t a;
    asm("{ .reg .u64 t; cvta.to.shared.u64 t, %1; cvt.u32.u64 %0, t; }" : "=r"(a) : "l"(p));
    return a;
}
__device__ __forceinline__ void cp_async16(uint32_t dst, const void* src) {
    asm volatile("cp.async.cg.shared.global [%0], [%1], 16;" :: "r"(dst), "l"(src));
}
__device__ __forceinline__ void cp_commit() {
    asm volatile("cp.async.commit_group;" ::: "memory");
}
template<int N> __device__ __forceinline__ void cp_wait() {
    asm volatile("cp.async.wait_group %0;" :: "n"(N) : "memory");
}
__device__ __forceinline__ uint32_t lds32(uint32_t addr) {
    uint32_t v;
    asm volatile("ld.shared.b32 %0, [%1];" : "=r"(v) : "r"(addr));
    return v;
}
__device__ __forceinline__ void mma_s8(int* c, const uint32_t* a, uint32_t b0, uint32_t b1) {
    asm volatile(
        "mma.sync.aligned.m16n8k32.row.col.s32.s8.s8.s32 "
        "{%0,%1,%2,%3}, {%4,%5,%6,%7}, {%8,%9}, {%0,%1,%2,%3};"
        : "+r"(c[0]), "+r"(c[1]), "+r"(c[2]), "+r"(c[3])
        : "r"(a[0]), "r"(a[1]), "r"(a[2]), "r"(a[3]), "r"(b0), "r"(b1));
}

// quantize one fp32 value (pre-scaled by inv) into two digits
__device__ __forceinline__ void quant2(float x, float inv, int8_t& d1, int8_t& d2) {
    int q = __float2int_rn(x * inv);
    q = max(-16383, min(16383, q));
    int a1 = (q + 64) >> 7;
    a1 = max(-128, min(127, a1));
    int a2 = q - (a1 << 7);
    d1 = (int8_t)a1;
    d2 = (int8_t)a2;
}

// ---------------------------------------------------------------------------
// Kernel 1: dequantize W row + per-row amax + int8 digit quantize
// one block per W row (4096 blocks x 512 threads, 8 values per thread)
// ---------------------------------------------------------------------------
__global__ __launch_bounds__(512)
void k_dequant_q(const float* __restrict__ grid,
                 const int*   __restrict__ qidxs)
{
    __shared__ float red[16];
    const int row = blockIdx.x;
    const int t = threadIdx.x;
    const int idx = qidxs[row * 512 + t];
    const float4* g = (const float4*)(grid + (size_t)idx * 8);
    float4 va = g[0], vb = g[1];
    float v[8] = {va.x, va.y, va.z, va.w, vb.x, vb.y, vb.z, vb.w};

    float lmax = 0.f;
    #pragma unroll
    for (int j = 0; j < 8; j++) lmax = fmaxf(lmax, fabsf(v[j]));
    #pragma unroll
    for (int o = 16; o > 0; o >>= 1)
        lmax = fmaxf(lmax, __shfl_xor_sync(0xFFFFFFFF, lmax, o));
    if ((t & 31) == 0) red[t >> 5] = lmax;
    __syncthreads();
    if (t == 0) {
        float m = red[0];
        #pragma unroll
        for (int w = 1; w < 16; w++) m = fmaxf(m, red[w]);
        red[0] = fmaxf(m, 1e-20f);
        g_sw[row] = red[0] * (1.0f / 16383.0f);
    }
    __syncthreads();
    const float inv = 16383.0f / red[0];

    int8_t h1[8], h2[8];
    #pragma unroll
    for (int j = 0; j < 8; j++) quant2(v[j], inv, h1[j], h2[j]);
    *(uint2*)(g_W1 + (size_t)row * NDIM + t * 8) = *(uint2*)h1;
    *(uint2*)(g_W2 + (size_t)row * NDIM + t * 8) = *(uint2*)h2;
}

// ---------------------------------------------------------------------------
// Kernel 2: X = fwht(input * SU)/64 -> per-row amax -> int8 digit quantize
// ---------------------------------------------------------------------------
__global__ __launch_bounds__(1024)
void k_fwht_in_q(const float* __restrict__ in,
                 const float* __restrict__ SU)
{
    __shared__ float s[NDIM];
    __shared__ float red[32];
    const int row = blockIdx.x;
    const int tid = threadIdx.x;
    const float* r = in + (size_t)row * NDIM;
    for (int i = tid; i < NDIM; i += 1024)
        s[i] = r[i] * SU[i];
    __syncthreads();
    for (int h = 1; h < NDIM; h <<= 1) {
        for (int p = tid; p < NDIM / 2; p += 1024) {
            int i = ((p & ~(h - 1)) << 1) | (p & (h - 1));
            int j = i + h;
            float a = s[i], b = s[j];
            s[i] = a + b;
            s[j] = a - b;
        }
        __syncthreads();
    }
    // per-row amax (on raw values; fold 1/64 into the scale)
    float lmax = 0.f;
    #pragma unroll
    for (int u = 0; u < 4; u++)
        lmax = fmaxf(lmax, fabsf(s[tid * 4 + u]));
    #pragma unroll
    for (int o = 16; o > 0; o >>= 1)
        lmax = fmaxf(lmax, __shfl_xor_sync(0xFFFFFFFF, lmax, o));
    if ((tid & 31) == 0) red[tid >> 5] = lmax;
    __syncthreads();
    if (tid == 0) {
        float m = red[0];
        #pragma unroll
        for (int w = 1; w < 32; w++) m = fmaxf(m, red[w]);
        red[0] = fmaxf(m, 1e-20f);
        g_sx[row] = red[0] * (0.015625f / 16383.0f);
    }
    __syncthreads();
    const float inv = 16383.0f / red[0];

    int8_t d1[4], d2[4];
    #pragma unroll
    for (int u = 0; u < 4; u++)
        quant2(s[tid * 4 + u], inv, d1[u], d2[u]);
    *(uint32_t*)(g_X1 + (size_t)row * NDIM + tid * 4) = *(uint32_t*)d1;
    *(uint32_t*)(g_X2 + (size_t)row * NDIM + tid * 4) = *(uint32_t*)d2;
}

// ---------------------------------------------------------------------------
// Kernel 3: IMMA digit GEMM  C[M,N] = X[M,K] * W[N,K]^T
// 128x128 tile, BK=64, 3-stage cp.async, 8 warps (2M x 4N), warp tile 64x32
// ---------------------------------------------------------------------------
__device__ __forceinline__ void issue_stage_loads(
    uint32_t sb, int buf, int c, int tid,
    const int8_t* A1, const int8_t* A2, const int8_t* B1, const int8_t* B2)
{
    const int k0 = c * BK;
    const uint32_t stage = sb + buf * STAGE_BYTES;
    const int8_t* gsrc[4] = {A1, A2, B1, B2};
    #pragma unroll
    for (int it = 0; it < 8; it++) {
        int idx = tid + it * 256;        // 0..2047
        int arr = idx >> 9;              // 0..3
        int cc  = idx & 511;
        int r   = cc >> 2;               // 0..127
        int kc  = cc & 3;                // 16B chunk
        int kblk = kc >> 1;
        int koff = (kc & 1) * 16;
        uint32_t dst = stage + arr * ARR_BYTES + kblk * KBLK_BYTES + r * ROWB + koff;
        cp_async16(dst, gsrc[arr] + (size_t)r * NDIM + k0 + kc * 16);
    }
}

__global__ __launch_bounds__(256, 1)
void k_gemm_imma(float* __restrict__ C)
{
    extern __shared__ char smem[];
    const uint32_t sb = smem_u32(smem);
    const int tid = threadIdx.x;
    const int wid = tid >> 5, lane = tid & 31;
    const int wm = wid & 1;          // 0..1 (M)
    const int wn = wid >> 1;         // 0..3 (N)

    const int8_t* A1 = g_X1 + (size_t)blockIdx.y * BM * NDIM;
    const int8_t* A2 = g_X2 + (size_t)blockIdx.y * BM * NDIM;
    const int8_t* B1 = g_W1 + (size_t)blockIdx.x * BN * NDIM;
    const int8_t* B2 = g_W2 + (size_t)blockIdx.x * BN * NDIM;

    int acc1[4][4][4];   // weight 16384: a1*b1
    int acc2[4][4][4];   // weight 128:   a1*b2 + a2*b1
    #pragma unroll
    for (int i = 0; i < 4; i++)
        #pragma unroll
        for (int j = 0; j < 4; j++)
            #pragma unroll
            for (int e = 0; e < 4; e++) { acc1[i][j][e] = 0; acc2[i][j][e] = 0; }

    issue_stage_loads(sb, 0, 0, tid, A1, A2, B1, B2); cp_commit();
    issue_stage_loads(sb, 1, 1, tid, A1, A2, B1, B2); cp_commit();

    const int lr = lane >> 2;        // 0..7
    const int lc = (lane & 3) * 4;   // byte col within k32

    int buf = 0;
    for (int c = 0; c < NKCHUNK; c++) {
        cp_wait<1>();
        __syncthreads();

        if (c + 2 < NKCHUNK)
            issue_stage_loads(sb, (buf + 2) % STAGES, c + 2, tid, A1, A2, B1, B2);
        cp_commit();

        const uint32_t stage = sb + buf * STAGE_BYTES;
        #pragma unroll
        for (int kblk = 0; kblk < 2; kblk++) {
            const uint32_t sA1 = stage + kblk * KBLK_BYTES;
            const uint32_t sA2 = sA1 + ARR_BYTES;
            const uint32_t sB1 = sA1 + 2 * ARR_BYTES;
            const uint32_t sB2 = sA1 + 3 * ARR_BYTES;

            uint32_t a1f[4][4], a2f[4][4];
            #pragma unroll
            for (int i = 0; i < 4; i++) {
                uint32_t base = (wm * 64 + i * 16 + lr) * ROWB + lc;
                a1f[i][0] = lds32(sA1 + base);
                a1f[i][1] = lds32(sA1 + base + 8 * ROWB);
                a1f[i][2] = lds32(sA1 + base + 16);
                a1f[i][3] = lds32(sA1 + base + 8 * ROWB + 16);
                a2f[i][0] = lds32(sA2 + base);
                a2f[i][1] = lds32(sA2 + base + 8 * ROWB);
                a2f[i][2] = lds32(sA2 + base + 16);
                a2f[i][3] = lds32(sA2 + base + 8 * ROWB + 16);
            }
            #pragma unroll
            for (int j = 0; j < 4; j++) {
                uint32_t nb = (wn * 32 + j * 8 + lr) * ROWB + lc;
                uint32_t b1_0 = lds32(sB1 + nb), b1_1 = lds32(sB1 + nb + 16);
                uint32_t b2_0 = lds32(sB2 + nb), b2_1 = lds32(sB2 + nb + 16);
                #pragma unroll
                for (int i = 0; i < 4; i++) {
                    mma_s8(acc1[i][j], a1f[i], b1_0, b1_1);   // a1*b1
                    mma_s8(acc2[i][j], a1f[i], b2_0, b2_1);   // a1*b2
                    mma_s8(acc2[i][j], a2f[i], b1_0, b1_1);   // a2*b1
                }
            }
        }
        buf = (buf + 1) % STAGES;
        __syncthreads();
    }

    // Epilogue: out = sx[row]*sw[col]*(16384*acc1 + 128*acc2)
    const int r0 = blockIdx.y * BM + wm * 64 + (lane >> 2);
    const int c0 = blockIdx.x * BN + wn * 32 + (lane & 3) * 2;
    #pragma unroll
    for (int i = 0; i < 4; i++) {
        const int ra = r0 + i * 16, rb = ra + 8;
        const float sxa = g_sx[ra], sxb = g_sx[rb];
        #pragma unroll
        for (int j = 0; j < 4; j++) {
            const int col = c0 + j * 8;
            const float sw0 = g_sw[col], sw1 = g_sw[col + 1];
            float v0 = fmaf(16384.f, (float)acc1[i][j][0], 128.f * (float)acc2[i][j][0]) * sxa * sw0;
            float v1 = fmaf(16384.f, (float)acc1[i][j][1], 128.f * (float)acc2[i][j][1]) * sxa * sw1;
            float v2 = fmaf(16384.f, (float)acc1[i][j][2], 128.f * (float)acc2[i][j][2]) * sxb * sw0;
            float v3 = fmaf(16384.f, (float)acc1[i][j][3], 128.f * (float)acc2[i][j][3]) * sxb * sw1;
            *(float2*)(C + (size_t)ra * MDIM + col) = make_float2(v0, v1);
            *(float2*)(C + (size_t)rb * MDIM + col) = make_float2(v2, v3);
        }
    }
}

// ---------------------------------------------------------------------------
// Kernel 4: out = fwht(out)/64 * SV, in place
// ---------------------------------------------------------------------------
__global__ __launch_bounds__(1024)
void k_fwht_out(float* __restrict__ io,
                const float* __restrict__ SV)
{
    __shared__ float s[MDIM];
    const int row = blockIdx.x;
    float* r = io + (size_t)row * MDIM;
    for (int i = threadIdx.x; i < MDIM; i += 1024)
        s[i] = r[i];
    __syncthreads();
    for (int h = 1; h < MDIM; h <<= 1) {
        for (int p = threadIdx.x; p < MDIM / 2; p += 1024) {
            int i = ((p & ~(h - 1)) << 1) | (p & (h - 1));
            int j = i + h;
            float a = s[i], b = s[j];
            s[i] = a + b;
            s[j] = a - b;
        }
        __syncthreads();
    }
    for (int i = threadIdx.x; i < MDIM; i += 1024)
        r[i] = s[i] * 0.015625f * SV[i];
}

// ---------------------------------------------------------------------------
extern "C" void kernel_launch(void* const* d_in, const int* in_sizes, int n_in,
                              void* d_out, int out_size)
{
    const float* input = (const float*)d_in[0];
    const float* SU    = (const float*)d_in[1];
    const float* SV    = (const float*)d_in[2];
    const float* grid  = (const float*)d_in[3];
    const int*   qidx  = (const int*)  d_in[4];
    float* out = (float*)d_out;
    (void)in_sizes; (void)n_in; (void)out_size;

    cudaFuncSetAttribute(k_gemm_imma, cudaFuncAttributeMaxDynamicSharedMemorySize, SMEM_TOTAL);

    k_dequant_q<<<MDIM, 512>>>(grid, qidx);
    k_fwht_in_q<<<MROWS, 1024>>>(input, SU);
    {
        dim3 gd(MDIM / BN, MROWS / BM);
        k_gemm_imma<<<gd, 256, SMEM_TOTAL>>>(out);
    }
    k_fwht_out<<<MROWS, 1024>>>(out, SV);
}

// round 5
// speedup vs baseline: 4.9306x; 4.9306x over previous
#include <cuda_runtime.h>
#include <cuda_fp16.h>
#include <cstdint>

#define MROWS 4096
#define NDIM  4096
#define MDIM  4096
#define NIDX  (MDIM * (NDIM / 8))

// ---------------- GEMM tiling ----------------
#define BM 128
#define BN 128
#define BK 32
#define STAGES 4
#define NKCHUNK (NDIM / BK)          // 128

// per stage: A,B each 128 rows x 80B (64B data = 32 fp16, +16B pad)
#define ROWB      80
#define ARR_BYTES (128 * ROWB)       // 10240
#define STAGE_BYTES (2 * ARR_BYTES)  // 20480
#define SMEM_TOTAL (STAGES * STAGE_BYTES)   // 81920

// Scratch (allocation-free rule)
__device__ __half g_X[(size_t)MROWS * NDIM];   // fwht(input*SU)/64 in fp16
__device__ __half g_W[(size_t)MDIM * NDIM];    // dequantized W in fp16

// ---------------- PTX helpers (legal at PTX target sm_103) ----------------
__device__ __forceinline__ uint32_t smem_u32(const void* p) {
    uint32_t a;
    asm("{ .reg .u64 t; cvta.to.shared.u64 t, %1; cvt.u32.u64 %0, t; }" : "=r"(a) : "l"(p));
    return a;
}
__device__ __forceinline__ void cp_async16(uint32_t dst, const void* src) {
    asm volatile("cp.async.cg.shared.global [%0], [%1], 16;" :: "r"(dst), "l"(src));
}
__device__ __forceinline__ void cp_commit() {
    asm volatile("cp.async.commit_group;" ::: "memory");
}
template<int N> __device__ __forceinline__ void cp_wait() {
    asm volatile("cp.async.wait_group %0;" :: "n"(N) : "memory");
}
__device__ __forceinline__ void ldm_x4(uint32_t* r, uint32_t addr) {
    asm volatile("ldmatrix.sync.aligned.m8n8.x4.shared.b16 {%0,%1,%2,%3}, [%4];"
                 : "=r"(r[0]), "=r"(r[1]), "=r"(r[2]), "=r"(r[3]) : "r"(addr));
}
__device__ __forceinline__ void mma_f16(float* c, const uint32_t* a, uint32_t b0, uint32_t b1) {
    asm volatile(
        "mma.sync.aligned.m16n8k16.row.col.f32.f16.f16.f32 "
        "{%0,%1,%2,%3}, {%4,%5,%6,%7}, {%8,%9}, {%0,%1,%2,%3};"
        : "+f"(c[0]), "+f"(c[1]), "+f"(c[2]), "+f"(c[3])
        : "r"(a[0]), "r"(a[1]), "r"(a[2]), "r"(a[3]), "r"(b0), "r"(b1));
}

// ---------------------------------------------------------------------------
// Kernel 1: dequantize W -> fp16
// ---------------------------------------------------------------------------
__global__ __launch_bounds__(256)
void k_dequant(const float* __restrict__ grid,
               const int*   __restrict__ qidxs)
{
    int t = blockIdx.x * blockDim.x + threadIdx.x;
    if (t >= NIDX) return;
    int idx = qidxs[t];
    const float4* g = (const float4*)(grid + (size_t)idx * 8);
    float4 a = g[0], b = g[1];
    __half h[8];
    h[0] = __float2half(a.x); h[1] = __float2half(a.y);
    h[2] = __float2half(a.z); h[3] = __float2half(a.w);
    h[4] = __float2half(b.x); h[5] = __float2half(b.y);
    h[6] = __float2half(b.z); h[7] = __float2half(b.w);
    *(uint4*)(g_W + (size_t)t * 8) = *(uint4*)h;
}

// ---------------------------------------------------------------------------
// Kernel 2: X = fwht(input * SU)/64 -> fp16
// ---------------------------------------------------------------------------
__global__ __launch_bounds__(1024)
void k_fwht_in(const float* __restrict__ in,
               const float* __restrict__ SU)
{
    __shared__ float s[NDIM];
    const int row = blockIdx.x;
    const float* r = in + (size_t)row * NDIM;
    for (int i = threadIdx.x; i < NDIM; i += 1024)
        s[i] = r[i] * SU[i];
    __syncthreads();
    for (int h = 1; h < NDIM; h <<= 1) {
        for (int p = threadIdx.x; p < NDIM / 2; p += 1024) {
            int i = ((p & ~(h - 1)) << 1) | (p & (h - 1));
            int j = i + h;
            float a = s[i], b = s[j];
            s[i] = a + b;
            s[j] = a - b;
        }
        __syncthreads();
    }
    // 4 contiguous fp16 per thread -> coalesced 64-bit stores
    {
        int i = threadIdx.x * 4;
        __half h[4];
        h[0] = __float2half(s[i + 0] * 0.015625f);
        h[1] = __float2half(s[i + 1] * 0.015625f);
        h[2] = __float2half(s[i + 2] * 0.015625f);
        h[3] = __float2half(s[i + 3] * 0.015625f);
        *(uint2*)(g_X + (size_t)row * NDIM + i) = *(uint2*)h;
    }
}

// ---------------------------------------------------------------------------
// Kernel 3: fp16 HMMA GEMM  C[M,N] = X[M,K] * W[N,K]^T
// 128x128 tile, BK=32, 4-stage cp.async, 8 warps (2M x 4N), 2 CTAs/SM
// ---------------------------------------------------------------------------
__device__ __forceinline__ void issue_stage_loads(
    uint32_t sb, int buf, int c, int tid,
    const __half* A, const __half* B)
{
    const int k0 = c * BK;
    const uint32_t stage = sb + buf * STAGE_BYTES;
    #pragma unroll
    for (int it = 0; it < 2; it++) {
        int idx = tid + it * 256;        // 0..511
        int r = idx >> 2;                // 0..127
        int cb = idx & 3;                // 16B chunk within 64B row
        cp_async16(stage + r * ROWB + cb * 16,
                   A + (size_t)r * NDIM + k0 + cb * 8);
    }
    #pragma unroll
    for (int it = 0; it < 2; it++) {
        int idx = tid + it * 256;
        int r = idx >> 2;
        int cb = idx & 3;
        cp_async16(stage + ARR_BYTES + r * ROWB + cb * 16,
                   B + (size_t)r * NDIM + k0 + cb * 8);
    }
}

__global__ __launch_bounds__(256, 2)
void k_gemm_hmma(float* __restrict__ C)
{
    extern __shared__ char smem[];
    const uint32_t sb = smem_u32(smem);
    const int tid = threadIdx.x;
    const int wid = tid >> 5, lane = tid & 31;
    const int wm = wid & 1;          // 0..1 (M)
    const int wn = wid >> 1;         // 0..3 (N)

    const __half* A = g_X + (size_t)blockIdx.y * BM * NDIM;
    const __half* B = g_W + (size_t)blockIdx.x * BN * NDIM;

    float acc[4][4][4];
    #pragma unroll
    for (int i = 0; i < 4; i++)
        #pragma unroll
        for (int j = 0; j < 4; j++)
            #pragma unroll
            for (int e = 0; e < 4; e++) acc[i][j][e] = 0.f;

    issue_stage_loads(sb, 0, 0, tid, A, B); cp_commit();
    issue_stage_loads(sb, 1, 1, tid, A, B); cp_commit();
    issue_stage_loads(sb, 2, 2, tid, A, B); cp_commit();

    const int lrow = lane & 15;
    const int lkb  = (lane >> 4) * 16;

    for (int c = 0; c < NKCHUNK; c++) {
        cp_wait<2>();
        __syncthreads();

        // refill the stage freed by iteration c-1
        if (c + 3 < NKCHUNK)
            issue_stage_loads(sb, (c + 3) & 3, c + 3, tid, A, B);
        cp_commit();

        const uint32_t stage = sb + (c & 3) * STAGE_BYTES;
        const uint32_t sA = stage;
        const uint32_t sB = stage + ARR_BYTES;

        #pragma unroll
        for (int kk = 0; kk < 2; kk++) {
            const int kb = kk * 32 + lkb;
            uint32_t af[4][4], bf[2][4];
            #pragma unroll
            for (int i = 0; i < 4; i++)
                ldm_x4(af[i], sA + (wm * 64 + i * 16 + lrow) * ROWB + kb);
            #pragma unroll
            for (int bt = 0; bt < 2; bt++)
                ldm_x4(bf[bt], sB + (wn * 32 + bt * 16 + lrow) * ROWB + kb);
            #pragma unroll
            for (int i = 0; i < 4; i++)
                #pragma unroll
                for (int j = 0; j < 4; j++) {
                    const int bt = j >> 1, odd = j & 1;
                    mma_f16(acc[i][j], af[i], bf[bt][odd], bf[bt][odd + 2]);
                }
        }
        __syncthreads();
    }

    // Epilogue
    const int crow0 = blockIdx.y * BM + wm * 64 + (lane >> 2);
    const int ccol0 = blockIdx.x * BN + wn * 32 + (lane & 3) * 2;
    #pragma unroll
    for (int i = 0; i < 4; i++)
        #pragma unroll
        for (int j = 0; j < 4; j++) {
            float* p0 = C + (size_t)(crow0 + i * 16)     * MDIM + ccol0 + j * 8;
            float* p1 = C + (size_t)(crow0 + i * 16 + 8) * MDIM + ccol0 + j * 8;
            *(float2*)p0 = make_float2(acc[i][j][0], acc[i][j][1]);
            *(float2*)p1 = make_float2(acc[i][j][2], acc[i][j][3]);
        }
}

// ---------------------------------------------------------------------------
// Kernel 4: out = fwht(out)/64 * SV, in place
// ---------------------------------------------------------------------------
__global__ __launch_bounds__(1024)
void k_fwht_out(float* __restrict__ io,
                const float* __restrict__ SV)
{
    __shared__ float s[MDIM];
    const int row = blockIdx.x;
    float* r = io + (size_t)row * MDIM;
    for (int i = threadIdx.x; i < MDIM; i += 1024)
        s[i] = r[i];
    __syncthreads();
    for (int h = 1; h < MDIM; h <<= 1) {
        for (int p = threadIdx.x; p < MDIM / 2; p += 1024) {
            int i = ((p & ~(h - 1)) << 1) | (p & (h - 1));
            int j = i + h;
            float a = s[i], b = s[j];
            s[i] = a + b;
            s[j] = a - b;
        }
        __syncthreads();
    }
    for (int i = threadIdx.x; i < MDIM; i += 1024)
        r[i] = s[i] * 0.015625f * SV[i];
}

// ---------------------------------------------------------------------------
extern "C" void kernel_launch(void* const* d_in, const int* in_sizes, int n_in,
                              void* d_out, int out_size)
{
    const float* input = (const float*)d_in[0];
    const float* SU    = (const float*)d_in[1];
    const float* SV    = (const float*)d_in[2];
    const float* grid  = (const float*)d_in[3];
    const int*   qidx  = (const int*)  d_in[4];
    float* out = (float*)d_out;
    (void)in_sizes; (void)n_in; (void)out_size;

    cudaFuncSetAttribute(k_gemm_hmma, cudaFuncAttributeMaxDynamicSharedMemorySize, SMEM_TOTAL);

    k_dequant<<<NIDX / 256, 256>>>(grid, qidx);
    k_fwht_in<<<MROWS, 1024>>>(input, SU);
    {
        dim3 gd(MDIM / BN, MROWS / BM);
        k_gemm_hmma<<<gd, 256, SMEM_TOTAL>>>(out);
    }
    k_fwht_out<<<MROWS, 1024>>>(out, SV);
}

// round 6
// speedup vs baseline: 5.5817x; 1.1320x over previous
#include <cuda_runtime.h>
#include <cuda_fp16.h>
#include <cstdint>

#define MROWS 4096
#define NDIM  4096
#define MDIM  4096
#define NIDX  (MDIM * (NDIM / 8))

// ---------------- GEMM tiling ----------------
#define BM 128
#define BN 128
#define BK 32
#define STAGES 4
#define NKCHUNK (NDIM / BK)          // 128

#define ROWB      80
#define ARR_BYTES (128 * ROWB)       // 10240
#define STAGE_BYTES (2 * ARR_BYTES)  // 20480
#define SMEM_TOTAL (STAGES * STAGE_BYTES)   // 81920

// Scratch (allocation-free rule)
__device__ __half g_X[(size_t)MROWS * NDIM];
__device__ __half g_W[(size_t)MDIM * NDIM];

// ---------------- PTX helpers ----------------
__device__ __forceinline__ uint32_t smem_u32(const void* p) {
    uint32_t a;
    asm("{ .reg .u64 t; cvta.to.shared.u64 t, %1; cvt.u32.u64 %0, t; }" : "=r"(a) : "l"(p));
    return a;
}
__device__ __forceinline__ void cp_async16(uint32_t dst, const void* src) {
    asm volatile("cp.async.cg.shared.global [%0], [%1], 16;" :: "r"(dst), "l"(src));
}
__device__ __forceinline__ void cp_commit() {
    asm volatile("cp.async.commit_group;" ::: "memory");
}
template<int N> __device__ __forceinline__ void cp_wait() {
    asm volatile("cp.async.wait_group %0;" :: "n"(N) : "memory");
}
__device__ __forceinline__ void ldm_x4(uint32_t* r, uint32_t addr) {
    asm volatile("ldmatrix.sync.aligned.m8n8.x4.shared.b16 {%0,%1,%2,%3}, [%4];"
                 : "=r"(r[0]), "=r"(r[1]), "=r"(r[2]), "=r"(r[3]) : "r"(addr));
}
__device__ __forceinline__ void mma_f16(float* c, const uint32_t* a, uint32_t b0, uint32_t b1) {
    asm volatile(
        "mma.sync.aligned.m16n8k16.row.col.f32.f16.f16.f32 "
        "{%0,%1,%2,%3}, {%4,%5,%6,%7}, {%8,%9}, {%0,%1,%2,%3};"
        : "+f"(c[0]), "+f"(c[1]), "+f"(c[2]), "+f"(c[3])
        : "r"(a[0]), "r"(a[1]), "r"(a[2]), "r"(a[3]), "r"(b0), "r"(b1));
}

// radix-4 butterfly on a float4 (stages h and 2h fused, contiguous quad)
__device__ __forceinline__ float4 bf4(float4 v) {
    float ab = v.x + v.y, amb = v.x - v.y;
    float cd = v.z + v.w, cmd = v.z - v.w;
    return make_float4(ab + cd, amb + cmd, ab - cd, amb - cmd);
}

// ---------------------------------------------------------------------------
// Kernel 1: dequantize W -> fp16
// ---------------------------------------------------------------------------
__global__ __launch_bounds__(256)
void k_dequant(const float* __restrict__ grid,
               const int*   __restrict__ qidxs)
{
    int t = blockIdx.x * blockDim.x + threadIdx.x;
    if (t >= NIDX) return;
    int idx = qidxs[t];
    const float4* g = (const float4*)(grid + (size_t)idx * 8);
    float4 a = g[0], b = g[1];
    __half h[8];
    h[0] = __float2half(a.x); h[1] = __float2half(a.y);
    h[2] = __float2half(a.z); h[3] = __float2half(a.w);
    h[4] = __float2half(b.x); h[5] = __float2half(b.y);
    h[6] = __float2half(b.z); h[7] = __float2half(b.w);
    *(uint4*)(g_W + (size_t)t * 8) = *(uint4*)h;
}

// ---------------------------------------------------------------------------
// Kernel 2: X = fwht(input * SU)/64 -> fp16   (radix-4, 1024 threads/row)
// ---------------------------------------------------------------------------
__global__ __launch_bounds__(1024)
void k_fwht_in(const float* __restrict__ in,
               const float* __restrict__ SU)
{
    __shared__ float s[NDIM];
    const int row = blockIdx.x;
    const int t = threadIdx.x;

    // load + SU scale + first two stages (h=1,2) in registers
    {
        float4 v  = ((const float4*)(in + (size_t)row * NDIM))[t];
        float4 su = ((const float4*)SU)[t];
        v.x *= su.x; v.y *= su.y; v.z *= su.z; v.w *= su.w;
        ((float4*)s)[t] = bf4(v);
    }
    __syncthreads();

    // 5 smem passes: h = 4,16,64,256,1024
    #pragma unroll
    for (int lh = 2; lh <= 10; lh += 2) {
        const int h = 1 << lh;
        const int i = ((t >> lh) << (lh + 2)) | (t & (h - 1));
        float a = s[i], b = s[i + h], c = s[i + 2 * h], d = s[i + 3 * h];
        float ab = a + b, amb = a - b, cd = c + d, cmd = c - d;
        s[i]         = ab + cd;
        s[i + h]     = amb + cmd;
        s[i + 2 * h] = ab - cd;
        s[i + 3 * h] = amb - cmd;
        __syncthreads();
    }

    // store fp16 (4 contiguous per thread)
    {
        float4 v = ((const float4*)s)[t];
        __half h4[4];
        h4[0] = __float2half(v.x * 0.015625f);
        h4[1] = __float2half(v.y * 0.015625f);
        h4[2] = __float2half(v.z * 0.015625f);
        h4[3] = __float2half(v.w * 0.015625f);
        *(uint2*)(g_X + (size_t)row * NDIM + t * 4) = *(uint2*)h4;
    }
}

// ---------------------------------------------------------------------------
// Kernel 3: fp16 HMMA GEMM  C[M,N] = X[M,K] * W[N,K]^T
// ---------------------------------------------------------------------------
__device__ __forceinline__ void issue_stage_loads(
    uint32_t sb, int buf, int c, int tid,
    const __half* A, const __half* B)
{
    const int k0 = c * BK;
    const uint32_t stage = sb + buf * STAGE_BYTES;
    #pragma unroll
    for (int it = 0; it < 2; it++) {
        int idx = tid + it * 256;
        int r = idx >> 2;
        int cb = idx & 3;
        cp_async16(stage + r * ROWB + cb * 16,
                   A + (size_t)r * NDIM + k0 + cb * 8);
    }
    #pragma unroll
    for (int it = 0; it < 2; it++) {
        int idx = tid + it * 256;
        int r = idx >> 2;
        int cb = idx & 3;
        cp_async16(stage + ARR_BYTES + r * ROWB + cb * 16,
                   B + (size_t)r * NDIM + k0 + cb * 8);
    }
}

__global__ __launch_bounds__(256, 2)
void k_gemm_hmma(float* __restrict__ C)
{
    extern __shared__ char smem[];
    const uint32_t sb = smem_u32(smem);
    const int tid = threadIdx.x;
    const int wid = tid >> 5, lane = tid & 31;
    const int wm = wid & 1;
    const int wn = wid >> 1;

    const __half* A = g_X + (size_t)blockIdx.y * BM * NDIM;
    const __half* B = g_W + (size_t)blockIdx.x * BN * NDIM;

    float acc[4][4][4];
    #pragma unroll
    for (int i = 0; i < 4; i++)
        #pragma unroll
        for (int j = 0; j < 4; j++)
            #pragma unroll
            for (int e = 0; e < 4; e++) acc[i][j][e] = 0.f;

    issue_stage_loads(sb, 0, 0, tid, A, B); cp_commit();
    issue_stage_loads(sb, 1, 1, tid, A, B); cp_commit();
    issue_stage_loads(sb, 2, 2, tid, A, B); cp_commit();

    const int lrow = lane & 15;
    const int lkb  = (lane >> 4) * 16;

    for (int c = 0; c < NKCHUNK; c++) {
        cp_wait<2>();
        __syncthreads();   // single barrier: stage c visible AND stage (c+3)&3 free

        if (c + 3 < NKCHUNK)
            issue_stage_loads(sb, (c + 3) & 3, c + 3, tid, A, B);
        cp_commit();

        const uint32_t stage = sb + (c & 3) * STAGE_BYTES;
        const uint32_t sA = stage;
        const uint32_t sB = stage + ARR_BYTES;

        #pragma unroll
        for (int kk = 0; kk < 2; kk++) {
            const int kb = kk * 32 + lkb;
            uint32_t af[4][4], bf[2][4];
            #pragma unroll
            for (int i = 0; i < 4; i++)
                ldm_x4(af[i], sA + (wm * 64 + i * 16 + lrow) * ROWB + kb);
            #pragma unroll
            for (int bt = 0; bt < 2; bt++)
                ldm_x4(bf[bt], sB + (wn * 32 + bt * 16 + lrow) * ROWB + kb);
            #pragma unroll
            for (int i = 0; i < 4; i++)
                #pragma unroll
                for (int j = 0; j < 4; j++) {
                    const int bt = j >> 1, odd = j & 1;
                    mma_f16(acc[i][j], af[i], bf[bt][odd], bf[bt][odd + 2]);
                }
        }
    }

    // Epilogue
    const int crow0 = blockIdx.y * BM + wm * 64 + (lane >> 2);
    const int ccol0 = blockIdx.x * BN + wn * 32 + (lane & 3) * 2;
    #pragma unroll
    for (int i = 0; i < 4; i++)
        #pragma unroll
        for (int j = 0; j < 4; j++) {
            float* p0 = C + (size_t)(crow0 + i * 16)     * MDIM + ccol0 + j * 8;
            float* p1 = C + (size_t)(crow0 + i * 16 + 8) * MDIM + ccol0 + j * 8;
            *(float2*)p0 = make_float2(acc[i][j][0], acc[i][j][1]);
            *(float2*)p1 = make_float2(acc[i][j][2], acc[i][j][3]);
        }
}

// ---------------------------------------------------------------------------
// Kernel 4: out = fwht(out)/64 * SV, in place (radix-4)
// ---------------------------------------------------------------------------
__global__ __launch_bounds__(1024)
void k_fwht_out(float* __restrict__ io,
                const float* __restrict__ SV)
{
    __shared__ float s[MDIM];
    const int row = blockIdx.x;
    const int t = threadIdx.x;
    float4* r4 = (float4*)(io + (size_t)row * MDIM);

    ((float4*)s)[t] = bf4(r4[t]);
    __syncthreads();

    #pragma unroll
    for (int lh = 2; lh <= 10; lh += 2) {
        const int h = 1 << lh;
        const int i = ((t >> lh) << (lh + 2)) | (t & (h - 1));
        float a = s[i], b = s[i + h], c = s[i + 2 * h], d = s[i + 3 * h];
        float ab = a + b, amb = a - b, cd = c + d, cmd = c - d;
        s[i]         = ab + cd;
        s[i + h]     = amb + cmd;
        s[i + 2 * h] = ab - cd;
        s[i + 3 * h] = amb - cmd;
        __syncthreads();
    }

    {
        float4 v = ((const float4*)s)[t];
        float4 sv = ((const float4*)SV)[t];
        r4[t] = make_float4(v.x * 0.015625f * sv.x, v.y * 0.015625f * sv.y,
                            v.z * 0.015625f * sv.z, v.w * 0.015625f * sv.w);
    }
}

// ---------------------------------------------------------------------------
extern "C" void kernel_launch(void* const* d_in, const int* in_sizes, int n_in,
                              void* d_out, int out_size)
{
    const float* input = (const float*)d_in[0];
    const float* SU    = (const float*)d_in[1];
    const float* SV    = (const float*)d_in[2];
    const float* grid  = (const float*)d_in[3];
    const int*   qidx  = (const int*)  d_in[4];
    float* out = (float*)d_out;
    (void)in_sizes; (void)n_in; (void)out_size;

    cudaFuncSetAttribute(k_gemm_hmma, cudaFuncAttributeMaxDynamicSharedMemorySize, SMEM_TOTAL);

    k_dequant<<<NIDX / 256, 256>>>(grid, qidx);
    k_fwht_in<<<MROWS, 1024>>>(input, SU);
    {
        dim3 gd(MDIM / BN, MROWS / BM);
        k_gemm_hmma<<<gd, 256, SMEM_TOTAL>>>(out);
    }
    k_fwht_out<<<MROWS, 1024>>>(out, SV);
}